// round 14
// baseline (speedup 1.0000x reference)
#include <cuda_runtime.h>
#include <cuda_bf16.h>

// Problem constants
#define BB 8
#define NPTS 16384
#define NG 512
#define GS 32
#define UK 512
#define CTX 256
#define R2 0.25f
#define K0 40            // dense iterations before first switch event
#define ACAP 8192        // active-list capacity (128KB smem)

// Output layout
#define OFF_GROUPS   0
#define OFF_CENTERS  262144
#define OFF_EMASK    270336
#define OFF_PMASK    272384

// ---------------- device scratch ----------------
__device__ float4             g_centers[BB * NG];
__device__ unsigned short     g_fz[BB][NPTS];                     // next-center-to-apply; 0xFFFF = active
__device__ unsigned long long g_cand[(size_t)BB * NG * UK];
__device__ int                g_cand_cnt[BB * NG];
__device__ int                g_group_len[BB];

__device__ __forceinline__ float d2_exact(float dx, float dy, float dz) {
    return __fadd_rn(__fadd_rn(__fmul_rn(dx, dx), __fmul_rn(dy, dy)), __fmul_rn(dz, dz));
}
__device__ __forceinline__ unsigned encf(float f) {
    unsigned u = __float_as_uint(f);
    return (u & 0x80000000u) ? ~u : (u | 0x80000000u);
}
__device__ __forceinline__ float decf(unsigned e) {
    return __uint_as_float((e & 0x80000000u) ? (e & 0x7FFFFFFFu) : ~e);
}
__device__ __forceinline__ unsigned redux_max_u32(unsigned v) {
    unsigned r; asm("redux.sync.max.u32 %0, %1, 0xffffffff;" : "=r"(r) : "r"(v)); return r;
}
__device__ __forceinline__ unsigned redux_min_u32(unsigned v) {
    unsigned r; asm("redux.sync.min.u32 %0, %1, 0xffffffff;" : "=r"(r) : "r"(v)); return r;
}
__device__ __forceinline__ unsigned redux_add_u32(unsigned v) {
    unsigned r; asm("redux.sync.add.u32 %0, %1, 0xffffffff;" : "=r"(r) : "r"(v)); return r;
}

__global__ void nop_kernel() {}

// =====================================================================
// K1: theta-frozen FPS. 1 CTA/batch, 1024 threads.
// smem: mind[16384] (64KB) + active list float4[8192] (128KB) + centers
// float4[512] (8KB) = 200KB. Frozen points carry stale mind; invariant:
// frozen true mind < th, so they cannot win between events.
// =====================================================================
#define FPS_SMEM (NPTS * 4 + ACAP * 16 + NG * 16)

__global__ void __launch_bounds__(1024, 1)
fps_kernel(const float4* __restrict__ pts, const int* __restrict__ lengths,
           float* __restrict__ out_centers) {
    extern __shared__ float dyn[];
    float*  __restrict__ mind = dyn;                    // [NPTS]
    float4* __restrict__ acrd = (float4*)(dyn + NPTS);  // [ACAP] {x,y,z,idx}
    float4* __restrict__ scc  = acrd + ACAP;            // [NG] center coords
    __shared__ unsigned long long s_wk[2][32];
    __shared__ float4 s_wc[2][32];
    __shared__ int s_cidx[NG];
    __shared__ int s_icnt[32];
    __shared__ int s_na;

    const int b = blockIdx.x, t = threadIdx.x;
    const int wid = t >> 5, lane = t & 31;
    const float4* __restrict__ P = pts + (size_t)b * NPTS;
    const int len = lengths[b];

#pragma unroll
    for (int i = 0; i < 16; i++) {
        int p = i * 1024 + t;
        bool va = (p < len);
        mind[p] = va ? 1e10f : -1e30f;
        g_fz[b][p] = va ? 0xFFFFu : 0u;      // invalid: frozen forever (never refreshed)
    }
    float4 v0 = __ldg(&P[0]);
    float wx = v0.x, wy = v0.y, wz = v0.z;
    if (t == 0) { s_cidx[0] = 0; scc[0] = make_float4(v0.x, v0.y, v0.z, 0.f); g_group_len[b] = 0; }
    float th = 0.f;
    int nA = 0;
    bool sparse = false;
    __syncthreads();

    for (int k = 1; k < NG; k++) {
        const int par = k & 1;
        // ---- update + per-thread value max ----
        float fm = -1e30f;
        if (!sparse) {
#pragma unroll
            for (int i = 0; i < 16; i++) {
                int p = i * 1024 + t;
                float4 pv = __ldg(&P[p]);
                float m = fminf(mind[p], d2_exact(pv.x - wx, pv.y - wy, pv.z - wz));
                mind[p] = m; fm = fmaxf(fm, m);
            }
        } else {
            for (int j = t; j < nA; j += 1024) {
                float4 a = acrd[j];
                int idx = __float_as_int(a.w);
                float m = fminf(mind[idx], d2_exact(a.x - wx, a.y - wy, a.z - wz));
                mind[idx] = m; fm = fmaxf(fm, m);
            }
        }
        // ---- warp argmax: value (redux), then min orig idx among matches ----
        unsigned ek = encf(fm), wm = redux_max_u32(ek);
        unsigned mybp = 0xFFFFFFFFu;
        float bx = 0.f, by = 0.f, bz = 0.f;
        if (ek == wm) {
            if (!sparse) {
#pragma unroll
                for (int i = 15; i >= 0; i--) { int p = i * 1024 + t; if (mind[p] == fm) mybp = (unsigned)p; }
            } else {
                for (int j = t; j < nA; j += 1024) {
                    float4 a = acrd[j];
                    unsigned idx = (unsigned)__float_as_int(a.w);
                    if (mind[idx] == fm && idx < mybp) { mybp = idx; bx = a.x; by = a.y; bz = a.z; }
                }
            }
        }
        unsigned wi = redux_min_u32(mybp);
        if (lane == 0) s_wk[par][wid] = ((unsigned long long)wm << 32) | (0xFFFFFFFFu - wi);
        if (ek == wm && mybp == wi && wi != 0xFFFFFFFFu) {     // unique owner lane
            if (!sparse) { float4 pv = __ldg(&P[wi]); bx = pv.x; by = pv.y; bz = pv.z; }
            s_wc[par][wid] = make_float4(bx, by, bz, 0.f);
        }
        __syncthreads();                                       // the one fast-path barrier

        unsigned long long kk = s_wk[par][lane];
        unsigned khi = (unsigned)(kk >> 32), klo = (unsigned)kk;
        unsigned mh = redux_max_u32(khi);
        unsigned ml = redux_max_u32((khi == mh) ? klo : 0u);
        unsigned long long best = ((unsigned long long)mh << 32) | ml;
        float vf = decf(mh);
        int wpt = (int)(0xFFFFFFFFu - ml);

        if (k != K0 && !(sparse && vf < th)) {
            // fast path: winner = active max (frozen provably can't win)
            int ww = __ffs(__ballot_sync(0xffffffffu, kk == best)) - 1;
            float4 wc = s_wc[par][ww];
            wx = wc.x; wy = wc.y; wz = wc.z;
            if (t == 0) { s_cidx[k] = wpt; scc[k] = make_float4(wx, wy, wz, 0.f); }
        } else {
            // ======== EVENT ========
            __syncthreads();
            float c = 0.5f * vf;
            // (a) refresh frozen band (stale >= c covers all possible winners
            //     and all points that could classify active under theta >= c)
#pragma unroll 1
            for (int i = 0; i < 16; i++) {
                int p = i * 1024 + t;
                unsigned fz = g_fz[b][p];
                float m = mind[p];
                if (fz != 0xFFFFu && m >= c) {
                    float4 pv = __ldg(&P[p]);
                    for (int cc = (int)fz; cc < k; cc++) {
                        float4 s = scc[cc];
                        m = fminf(m, d2_exact(pv.x - s.x, pv.y - s.y, pv.z - s.z));
                    }
                    mind[p] = m;
                    g_fz[b][p] = (unsigned short)k;
                }
            }
            __syncthreads();
            // (b) exact global argmax over all slots
            float fm2 = -1e30f;
#pragma unroll
            for (int i = 0; i < 16; i++) fm2 = fmaxf(fm2, mind[i * 1024 + t]);
            unsigned ek2 = encf(fm2), wm2 = redux_max_u32(ek2);
            unsigned mb2 = 0xFFFFFFFFu;
            if (ek2 == wm2) {
#pragma unroll
                for (int i = 15; i >= 0; i--) { int p = i * 1024 + t; if (mind[p] == fm2) mb2 = (unsigned)p; }
            }
            unsigned wi2 = redux_min_u32(mb2);
            if (lane == 0) s_wk[par][wid] = ((unsigned long long)wm2 << 32) | (0xFFFFFFFFu - wi2);
            if (ek2 == wm2 && mb2 == wi2 && wi2 != 0xFFFFFFFFu) {
                float4 pv = __ldg(&P[wi2]);
                s_wc[par][wid] = make_float4(pv.x, pv.y, pv.z, 0.f);
            }
            __syncthreads();
            unsigned long long k2 = s_wk[par][lane];
            unsigned h2 = (unsigned)(k2 >> 32), l2 = (unsigned)k2;
            unsigned mh2 = redux_max_u32(h2);
            unsigned ml2 = redux_max_u32((h2 == mh2) ? l2 : 0u);
            unsigned long long b2 = ((unsigned long long)mh2 << 32) | ml2;
            float vnew = decf(mh2);
            wpt = (int)(0xFFFFFFFFu - ml2);
            int ww2 = __ffs(__ballot_sync(0xffffffffu, k2 == b2)) - 1;
            float4 wc2 = s_wc[par][ww2];
            wx = wc2.x; wy = wc2.y; wz = wc2.z;
            if (t == 0) { s_cidx[k] = wpt; scc[k] = make_float4(wx, wy, wz, 0.f); }
            // (c) theta = vnew/2, escalated until active count fits ACAP
            float theta = 0.5f * vnew;
            for (int r = 0; r < 6; r++) {
                int my = 0;
#pragma unroll
                for (int i = 0; i < 16; i++) my += (mind[i * 1024 + t] >= theta) ? 1 : 0;
                unsigned ws = redux_add_u32((unsigned)my);
                if (lane == 0) s_icnt[wid] = (int)ws;
                __syncthreads();
                int tot = (int)redux_add_u32((unsigned)s_icnt[lane]);
                if (tot <= ACAP) break;
                theta = (r >= 4) ? vnew : __fmul_rn(0.5f, __fadd_rn(theta, vnew));
                __syncthreads();
            }
            th = theta;
            // (d) rebuild compacted active list; freeze the rest (exact, fz=k)
            if (t == 0) s_na = 0;
            __syncthreads();
#pragma unroll 1
            for (int i = 0; i < 16; i++) {
                int p = i * 1024 + t;
                if (mind[p] >= theta) {
                    int pos = atomicAdd(&s_na, 1);
                    if (pos < ACAP) {
                        float4 pv = __ldg(&P[p]);
                        acrd[pos] = make_float4(pv.x, pv.y, pv.z, __int_as_float(p));
                        g_fz[b][p] = 0xFFFFu;
                    } else {
                        g_fz[b][p] = (unsigned short)k;   // unreachable (count-checked)
                    }
                } else if (g_fz[b][p] == 0xFFFFu) {
                    g_fz[b][p] = (unsigned short)k;
                }
            }
            __syncthreads();
            nA = min(s_na, ACAP);
            sparse = true;
        }
    }
    __syncthreads();

    // tail: gather centers (all 4 channels incl. energy)
    if (t < NG) {
        int p = s_cidx[t];
        float4 v = __ldg(&P[p]);
        g_centers[b * NG + t] = v;
        if (t < CTX) ((float4*)out_centers)[b * CTX + t] = v;
    }
}

// =====================================================================
// K2: ball query, warp-per-center, MLP=8 (unchanged, proven 93us->?)
// =====================================================================
__global__ __launch_bounds__(256, 4)
void ballquery_kernel(const float4* __restrict__ pts, const int* __restrict__ lengths) {
    const int b = blockIdx.y;
    const int wid = threadIdx.x >> 5, lane = threadIdx.x & 31;
    const int gi = blockIdx.x * 8 + wid;
    const int len = lengths[b];
    const float4* __restrict__ P = pts + (size_t)b * NPTS;
    const unsigned lt = (1u << lane) - 1u;

    float4 cc = g_centers[b * NG + gi];
    const float cx = cc.x, cy = cc.y, cz = cc.z;
    unsigned long long* __restrict__ buf = g_cand + (size_t)(b * NG + gi) * UK;

    int cnt = 0;
    for (int p0 = 0; p0 < NPTS && cnt < UK; p0 += 256) {
        float4 v[8];
#pragma unroll
        for (int j = 0; j < 8; j++)
            v[j] = __ldg(&P[p0 + j * 32 + lane]);
#pragma unroll
        for (int j = 0; j < 8; j++) {
            int p = p0 + j * 32 + lane;
            bool pred = (p < len) && (d2_exact(v[j].x - cx, v[j].y - cy, v[j].z - cz) < R2);
            unsigned m = __ballot_sync(0xffffffffu, pred);
            if (m) {
                int rnk = cnt + __popc(m & lt);
                if (pred && rnk < UK) {
                    unsigned eb = __float_as_uint(v[j].w);
                    unsigned ekey = (eb & 0x80000000u) ? ~eb : (eb | 0x80000000u);
                    buf[rnk] = ((unsigned long long)ekey << 32)
                             | (unsigned)(0xFFFFFFFFu - (unsigned)p);
                }
                cnt += __popc(m);
                if (cnt >= UK) { cnt = UK; break; }
            }
        }
    }
    if (lane == 0) g_cand_cnt[b * NG + gi] = cnt;
}

// =====================================================================
// K3: per-group adaptive bitonic sort + emit (unchanged)
// =====================================================================
__global__ __launch_bounds__(256, 8)
void sort_emit_kernel(const float4* __restrict__ pts,
                      float* __restrict__ out_groups,
                      float* __restrict__ out_pmask) {
    const int gi = blockIdx.x;
    const int b  = blockIdx.y;
    const int g  = b * NG + gi;
    const int t  = threadIdx.x;

    __shared__ unsigned long long s[UK];
    const int cnt = g_cand_cnt[g];
    const unsigned long long* __restrict__ src = g_cand + (size_t)g * UK;

    int M = GS;
    while (M < cnt) M <<= 1;

    for (int i = t; i < M; i += 256)
        s[i] = (i < cnt) ? src[i] : 0ull;

    for (int kk = 2; kk <= M; kk <<= 1) {
        for (int j = kk >> 1; j > 0; j >>= 1) {
            __syncthreads();
            for (int e = t; e < M; e += 256) {
                int l = e ^ j;
                if (l > e) {
                    unsigned long long a = s[e], c = s[l];
                    bool dsc = ((e & kk) == 0);
                    bool sw = dsc ? (a < c) : (a > c);
                    if (sw) { s[e] = c; s[l] = a; }
                }
            }
        }
    }
    __syncthreads();

    const int pl = min(cnt, GS);
    if (t == 0 && cnt >= GS) atomicAdd(&g_group_len[b], 1);

    if (gi < CTX) {
        if (t < GS * 4) {
            int slot = t >> 2, ch = t & 3;
            int ss = (slot < pl) ? slot : 0;
            unsigned p = 0xFFFFFFFFu - (unsigned)(s[ss] & 0xFFFFFFFFull);
            const float* pp = (const float*)(pts + ((size_t)b * NPTS + p));
            out_groups[(((size_t)(b * CTX + gi)) * GS + slot) * 4 + ch] = pp[ch];
        } else if (t < GS * 4 + GS) {
            int slot = t - GS * 4;
            out_pmask[(size_t)(b * CTX + gi) * GS + slot] = (slot < pl) ? 1.0f : 0.0f;
        }
    }
}

// =====================================================================
// K4: embedding mask
// =====================================================================
__global__ void emask_kernel(float* __restrict__ em) {
    int b = blockIdx.x, t = threadIdx.x;
    em[b * CTX + t] = (t < g_group_len[b]) ? 1.0f : 0.0f;
}

// =====================================================================
extern "C" void kernel_launch(void* const* d_in, const int* in_sizes, int n_in,
                              void* d_out, int out_size) {
    const float4* pts = (const float4*)d_in[0];
    const int*   lens = (const int*)d_in[1];
    float* out = (float*)d_out;

    cudaFuncSetAttribute(fps_kernel,
                         cudaFuncAttributeMaxDynamicSharedMemorySize, FPS_SMEM);

    // fps is launch #4 -> ncu capture verifies the lazy-FPS change
    nop_kernel<<<1, 32>>>();
    nop_kernel<<<1, 32>>>();
    nop_kernel<<<1, 32>>>();
    fps_kernel<<<BB, 1024, FPS_SMEM>>>(pts, lens, out + OFF_CENTERS);
    ballquery_kernel<<<dim3(64, BB), 256>>>(pts, lens);
    sort_emit_kernel<<<dim3(NG, BB), 256>>>(pts, out + OFF_GROUPS, out + OFF_PMASK);
    emask_kernel<<<BB, CTX>>>(out + OFF_EMASK);
}

// round 15
// speedup vs baseline: 1.6003x; 1.6003x over previous
#include <cuda_runtime.h>
#include <cuda_bf16.h>

// Problem constants
#define BB 8
#define NPTS 16384
#define NG 512          // NUM_GROUPS
#define GS 32           // GROUP_SIZE
#define UK 512          // UPSCALE_K
#define CTX 256         // CONTEXT
#define R2 0.25f        // RADIUS^2

// Output layout (float32, flattened concat of the reference tuple)
#define OFF_GROUPS   0          // 8*256*32*4 = 262144
#define OFF_CENTERS  262144     // 8*256*4   = 8192
#define OFF_EMASK    270336     // 8*256     = 2048
#define OFF_PMASK    272384     // 8*256*32  = 65536

// ---------------- device scratch (no allocations allowed) ----------------
__device__ float4             g_centers[BB * NG];
__device__ unsigned long long g_cand[(size_t)BB * NG * UK];       // 16MB candidate keys
__device__ int                g_cand_cnt[BB * NG];
__device__ int                g_group_len[BB];

// exact (no fma contraction) squared distance, reduce order ((dx^2+dy^2)+dz^2)
__device__ __forceinline__ float d2_exact(float dx, float dy, float dz) {
    return __fadd_rn(__fadd_rn(__fmul_rn(dx, dx), __fmul_rn(dy, dy)), __fmul_rn(dz, dz));
}

__device__ __forceinline__ unsigned encf(float f) {       // order-preserving float->u32
    unsigned u = __float_as_uint(f);
    return (u & 0x80000000u) ? ~u : (u | 0x80000000u);
}
__device__ __forceinline__ unsigned redux_max_u32(unsigned v) {
    unsigned r; asm("redux.sync.max.u32 %0, %1, 0xffffffff;" : "=r"(r) : "r"(v)); return r;
}
__device__ __forceinline__ unsigned redux_min_u32(unsigned v) {
    unsigned r; asm("redux.sync.min.u32 %0, %1, 0xffffffff;" : "=r"(r) : "r"(v)); return r;
}

// packed f32x2 helpers (two independent fp32 RN lanes — bit-exact vs scalar).
// NOTE: only add/mul/fma exist in f32x2 form on sm_103a; min/max stay scalar.
#define PACK2(o, lo, hi)  asm("mov.b64 %0, {%1, %2};" : "=l"(o) : "f"(lo), "f"(hi))
#define UNPACK2(lo, hi, i) asm("mov.b64 {%0, %1}, %2;" : "=f"(lo), "=f"(hi) : "l"(i))
#define ADDX2(o, a, b)    asm("add.rn.f32x2 %0, %1, %2;" : "=l"(o) : "l"(a), "l"(b))
#define MULX2(o, a, b)    asm("mul.rn.f32x2 %0, %1, %2;" : "=l"(o) : "l"(a), "l"(b))

// =====================================================================
// K1: dense FPS (R12-proven core). 1024 threads, 8 point-pairs/thread,
// X/Y packed in registers, z in smem. z-pairs are stored PER-THREAD-
// CONTIGUOUS: thread t's 8 pairs occupy u64 slots [t*8 .. t*8+7], read
// as 4x LDS.128. Single barrier/iter; winner recomputed in every warp.
// =====================================================================
#define FPS_T 1024
#define PAIRS 8
#define FPS_SMEM (NPTS * 8 + NPTS * 4)   // sxy[NPTS] float2 + z pairs float2[NPTS/2]

__global__ void __launch_bounds__(FPS_T, 1)
fps_kernel(const float4* __restrict__ pts, const int* __restrict__ lengths,
           float* __restrict__ out_centers /* d_out + OFF_CENTERS */) {
    extern __shared__ float smem[];
    float2* __restrict__ sxy = (float2*)smem;              // [NPTS] by point
    float2* __restrict__ szp = (float2*)(smem + 2 * NPTS); // [NPTS/2] z pairs (thread-contig)
    __shared__ unsigned long long s_wk[2][32];             // double-buffered warp keys
    __shared__ int s_cidx[NG];

    const int b = blockIdx.x, t = threadIdx.x;
    const int wid = t >> 5, lane = t & 31;
    const float4* __restrict__ P = pts + (size_t)b * NPTS;
    const int len = lengths[b];

    unsigned long long X[PAIRS], Y[PAIRS];
    float mind[2 * PAIRS];

#pragma unroll
    for (int i = 0; i < PAIRS; i++) {
        int q = i * FPS_T + t;                 // global pair id (for point indices)
        int p0 = 2 * q, p1 = 2 * q + 1;
        float4 v0 = P[p0], v1 = P[p1];
        bool va = (p0 < len), vb = (p1 < len);
        float x0 = va ? v0.x : 1e18f, y0 = va ? v0.y : 1e18f, z0 = va ? v0.z : 1e18f;
        float x1 = vb ? v1.x : 1e18f, y1 = vb ? v1.y : 1e18f, z1 = vb ? v1.z : 1e18f;
        PACK2(X[i], x0, x1);
        PACK2(Y[i], y0, y1);
        sxy[p0] = make_float2(x0, y0);
        sxy[p1] = make_float2(x1, y1);
        szp[t * PAIRS + i] = make_float2(z0, z1);   // thread-contiguous slot
        mind[2 * i]     = va ? 1e10f : -1e30f;
        mind[2 * i + 1] = vb ? 1e10f : -1e30f;
    }
    float4 v0 = __ldg(&P[0]);
    float wx = v0.x, wy = v0.y, wz = v0.z;
    int wpt = 0;
    if (t == 0) { s_cidx[0] = 0; g_group_len[b] = 0; }
    __syncthreads();

    for (int k = 1; k < NG; k++) {
        unsigned long long nCx, nCy, nCz;
        PACK2(nCx, -wx, -wx);
        PACK2(nCy, -wy, -wy);
        PACK2(nCz, -wz, -wz);

        float fm = -1e30f;
#pragma unroll
        for (int h = 0; h < PAIRS / 2; h++) {         // LDS.128: two z-pairs at once
            float4 z4 = ((const float4*)szp)[t * (PAIRS / 2) + h];
#pragma unroll
            for (int s = 0; s < 2; s++) {
                int i = 2 * h + s;
                unsigned long long Zp, dx, dy, dz, sx, sy, sz, s1, d2p;
                PACK2(Zp, s ? z4.z : z4.x, s ? z4.w : z4.y);
                ADDX2(dx, X[i], nCx);
                ADDX2(dy, Y[i], nCy);
                ADDX2(dz, Zp,  nCz);
                MULX2(sx, dx, dx);
                MULX2(sy, dy, dy);
                MULX2(sz, dz, dz);
                ADDX2(s1, sx, sy);                    // (dx^2 + dy^2)
                ADDX2(d2p, s1, sz);                   // ... + dz^2 (same order as scalar)
                float lo, hi;
                UNPACK2(lo, hi, d2p);
                float m0 = fminf(mind[2 * i],     lo);
                float m1 = fminf(mind[2 * i + 1], hi);
                mind[2 * i] = m0; mind[2 * i + 1] = m1;
                fm = fmaxf(fm, fmaxf(m0, m1));
            }
        }

        // warp argmax: max value (redux), min point index among matches
        unsigned ek = encf(fm);
        unsigned wm = redux_max_u32(ek);
        unsigned mybp = 0xFFFFFFFFu;
        if (ek == wm) {                      // predicated rescan (winning lanes only)
#pragma unroll
            for (int i = PAIRS - 1; i >= 0; i--) {
                int q = i * FPS_T + t;
                if (mind[2 * i + 1] == fm) mybp = (unsigned)(2 * q + 1);
                if (mind[2 * i]     == fm) mybp = (unsigned)(2 * q);
            }
        }
        unsigned wi = redux_min_u32(mybp);
        const int par = k & 1;
        if (lane == 0)
            s_wk[par][wid] = ((unsigned long long)wm << 32) | (0xFFFFFFFFu - wi);
        __syncthreads();                     // ONE barrier per iteration

        // every warp redundantly reduces the 32 keys -> identical winner
        unsigned long long kk = s_wk[par][lane];
        unsigned khi = (unsigned)(kk >> 32), klo = (unsigned)kk;
        unsigned mh = redux_max_u32(khi);
        unsigned ml = redux_max_u32((khi == mh) ? klo : 0u);
        wpt = (int)(0xFFFFFFFFu - ml);
        float2 xy = sxy[wpt];
        // z lives at thread-contig slot: pair q = wpt>>1, owner thread q%1024, slot q/1024
        int q = wpt >> 1;
        float2 z2 = szp[(q & 1023) * PAIRS + (q >> 10)];
        wx = xy.x; wy = xy.y; wz = (wpt & 1) ? z2.y : z2.x;
        if (t == 0) s_cidx[k] = wpt;
    }
    __syncthreads();

    // tail: gather centers (all 4 channels incl. energy)
    if (t < NG) {
        int p = s_cidx[t];
        float4 v = __ldg(&P[p]);
        g_centers[b * NG + t] = v;
        if (t < CTX) ((float4*)out_centers)[b * CTX + t] = v;
    }
}

// =====================================================================
// K2: ball query, warp-per-center, MLP=8. grid (64, 8), 256 threads.
// Also accumulates g_group_len (count of groups with cnt >= GS) so the
// embedding mask can be emitted by sort_emit without a 4th kernel.
// =====================================================================
__global__ __launch_bounds__(256, 4)
void ballquery_kernel(const float4* __restrict__ pts, const int* __restrict__ lengths) {
    const int b = blockIdx.y;
    const int wid = threadIdx.x >> 5, lane = threadIdx.x & 31;
    const int gi = blockIdx.x * 8 + wid;          // center index 0..511
    const int len = lengths[b];
    const float4* __restrict__ P = pts + (size_t)b * NPTS;
    const unsigned lt = (1u << lane) - 1u;

    float4 cc = g_centers[b * NG + gi];
    const float cx = cc.x, cy = cc.y, cz = cc.z;
    unsigned long long* __restrict__ buf = g_cand + (size_t)(b * NG + gi) * UK;

    int cnt = 0;
    for (int p0 = 0; p0 < NPTS && cnt < UK; p0 += 256) {
        float4 v[8];
#pragma unroll
        for (int j = 0; j < 8; j++)                // 8 independent loads: MLP=8
            v[j] = __ldg(&P[p0 + j * 32 + lane]);
#pragma unroll
        for (int j = 0; j < 8; j++) {              // ordered ballot rounds
            int p = p0 + j * 32 + lane;
            bool pred = (p < len) && (d2_exact(v[j].x - cx, v[j].y - cy, v[j].z - cz) < R2);
            unsigned m = __ballot_sync(0xffffffffu, pred);
            if (m) {
                int rnk = cnt + __popc(m & lt);
                if (pred && rnk < UK) {
                    unsigned eb = __float_as_uint(v[j].w);
                    unsigned ekey = (eb & 0x80000000u) ? ~eb : (eb | 0x80000000u);
                    buf[rnk] = ((unsigned long long)ekey << 32)
                             | (unsigned)(0xFFFFFFFFu - (unsigned)p);
                }
                cnt += __popc(m);
                if (cnt >= UK) { cnt = UK; break; }
            }
        }
    }
    if (lane == 0) {
        g_cand_cnt[b * NG + gi] = cnt;
        if (cnt >= GS) atomicAdd(&g_group_len[b], 1);   // group fully populated
    }
}

// =====================================================================
// K3: per-group adaptive bitonic sort + emit groups/point_mask/emask.
// g_group_len is final (ballquery kernel boundary precedes this launch),
// so the embedding-mask element for this group is written here too.
// =====================================================================
__global__ __launch_bounds__(256, 8)
void sort_emit_kernel(const float4* __restrict__ pts,
                      float* __restrict__ out_groups /* d_out */,
                      float* __restrict__ out_pmask  /* d_out + OFF_PMASK */,
                      float* __restrict__ out_emask  /* d_out + OFF_EMASK */) {
    const int gi = blockIdx.x;
    const int b  = blockIdx.y;
    const int g  = b * NG + gi;
    const int t  = threadIdx.x;

    __shared__ unsigned long long s[UK];
    const int cnt = g_cand_cnt[g];
    const unsigned long long* __restrict__ src = g_cand + (size_t)g * UK;

    int M = GS;
    while (M < cnt) M <<= 1;                       // 32..512, CTA-uniform

    for (int i = t; i < M; i += 256)
        s[i] = (i < cnt) ? src[i] : 0ull;

    for (int kk = 2; kk <= M; kk <<= 1) {
        for (int j = kk >> 1; j > 0; j >>= 1) {
            __syncthreads();
            for (int e = t; e < M; e += 256) {
                int l = e ^ j;
                if (l > e) {
                    unsigned long long a = s[e], c = s[l];
                    bool dsc = ((e & kk) == 0);
                    bool sw = dsc ? (a < c) : (a > c);
                    if (sw) { s[e] = c; s[l] = a; }
                }
            }
        }
    }
    __syncthreads();

    const int pl = min(cnt, GS);

    if (gi < CTX) {
        if (t < GS * 4) {
            int slot = t >> 2, ch = t & 3;
            int ss = (slot < pl) ? slot : 0;
            unsigned p = 0xFFFFFFFFu - (unsigned)(s[ss] & 0xFFFFFFFFull);
            const float* pp = (const float*)(pts + ((size_t)b * NPTS + p));
            out_groups[(((size_t)(b * CTX + gi)) * GS + slot) * 4 + ch] = pp[ch];
        } else if (t < GS * 4 + GS) {
            int slot = t - GS * 4;
            out_pmask[(size_t)(b * CTX + gi) * GS + slot] = (slot < pl) ? 1.0f : 0.0f;
        } else if (t == GS * 4 + GS) {
            out_emask[b * CTX + gi] = (gi < g_group_len[b]) ? 1.0f : 0.0f;
        }
    }
}

// =====================================================================
extern "C" void kernel_launch(void* const* d_in, const int* in_sizes, int n_in,
                              void* d_out, int out_size) {
    const float4* pts = (const float4*)d_in[0];   // (8,16384,4) f32
    const int*   lens = (const int*)d_in[1];      // (8,)
    float* out = (float*)d_out;

    cudaFuncSetAttribute(fps_kernel,
                         cudaFuncAttributeMaxDynamicSharedMemorySize, FPS_SMEM);

    fps_kernel<<<BB, FPS_T, FPS_SMEM>>>(pts, lens, out + OFF_CENTERS);
    ballquery_kernel<<<dim3(64, BB), 256>>>(pts, lens);
    sort_emit_kernel<<<dim3(NG, BB), 256>>>(pts, out + OFF_GROUPS,
                                            out + OFF_PMASK, out + OFF_EMASK);
}

// round 16
// speedup vs baseline: 2.1554x; 1.3469x over previous
#include <cuda_runtime.h>
#include <cuda_bf16.h>

// Problem constants
#define BB 8
#define NPTS 16384
#define NG 512          // NUM_GROUPS
#define GS 32           // GROUP_SIZE
#define UK 512          // UPSCALE_K
#define CTX 256         // CONTEXT
#define R2 0.25f        // RADIUS^2

// Output layout (float32, flattened concat of the reference tuple)
#define OFF_GROUPS   0          // 8*256*32*4 = 262144
#define OFF_CENTERS  262144     // 8*256*4   = 8192
#define OFF_EMASK    270336     // 8*256     = 2048
#define OFF_PMASK    272384     // 8*256*32  = 65536

// ---------------- device scratch (no allocations allowed) ----------------
__device__ float4             g_centers[BB * NG];
__device__ unsigned long long g_cand[(size_t)BB * NG * UK];       // 16MB candidate keys
__device__ int                g_cand_cnt[BB * NG];
__device__ int                g_group_len[BB];

// exact (no fma contraction) squared distance, reduce order ((dx^2+dy^2)+dz^2)
__device__ __forceinline__ float d2_exact(float dx, float dy, float dz) {
    return __fadd_rn(__fadd_rn(__fmul_rn(dx, dx), __fmul_rn(dy, dy)), __fmul_rn(dz, dz));
}

__device__ __forceinline__ unsigned encf(float f) {       // order-preserving float->u32
    unsigned u = __float_as_uint(f);
    return (u & 0x80000000u) ? ~u : (u | 0x80000000u);
}
__device__ __forceinline__ unsigned redux_max_u32(unsigned v) {
    unsigned r; asm("redux.sync.max.u32 %0, %1, 0xffffffff;" : "=r"(r) : "r"(v)); return r;
}
__device__ __forceinline__ unsigned redux_min_u32(unsigned v) {
    unsigned r; asm("redux.sync.min.u32 %0, %1, 0xffffffff;" : "=r"(r) : "r"(v)); return r;
}

// packed f32x2 helpers (two independent fp32 RN lanes — bit-exact vs scalar).
// NOTE: only add/mul/fma exist in f32x2 form on sm_103a; min/max stay scalar.
#define PACK2(o, lo, hi)  asm("mov.b64 %0, {%1, %2};" : "=l"(o) : "f"(lo), "f"(hi))
#define UNPACK2(lo, hi, i) asm("mov.b64 {%0, %1}, %2;" : "=f"(lo), "=f"(hi) : "l"(i))
#define ADDX2(o, a, b)    asm("add.rn.f32x2 %0, %1, %2;" : "=l"(o) : "l"(a), "l"(b))
#define MULX2(o, a, b)    asm("mul.rn.f32x2 %0, %1, %2;" : "=l"(o) : "l"(a), "l"(b))

// =====================================================================
// K1: dense FPS — R12 core VERBATIM (measured 542us, issue 64.7%).
// 1024 threads, 8 point-pairs/thread. X/Y packed in registers, z pairs
// in smem with INTERLEAVED layout szp[q], q = i*1024 + t: consecutive
// lanes read consecutive float2 -> conflict-free LDS.64 (R15 lesson:
// thread-contiguous LDS.128 layout caused 64B lane stride = conflicts).
// Single barrier/iter; winner recomputed redundantly in every warp.
// =====================================================================
#define FPS_T 1024
#define PAIRS 8
#define FPS_SMEM (NPTS * 8 + NPTS * 4)   // sxy[NPTS] float2 + z pairs float2[NPTS/2]

__global__ void __launch_bounds__(FPS_T, 1)
fps_kernel(const float4* __restrict__ pts, const int* __restrict__ lengths,
           float* __restrict__ out_centers /* d_out + OFF_CENTERS */) {
    extern __shared__ float smem[];
    float2* __restrict__ sxy = (float2*)smem;              // [NPTS] by point
    float2* __restrict__ szp = (float2*)(smem + 2 * NPTS); // [NPTS/2] z pairs (interleaved)
    __shared__ unsigned long long s_wk[2][32];             // double-buffered warp keys
    __shared__ int s_cidx[NG];

    const int b = blockIdx.x, t = threadIdx.x;
    const int wid = t >> 5, lane = t & 31;
    const float4* __restrict__ P = pts + (size_t)b * NPTS;
    const int len = lengths[b];

    unsigned long long X[PAIRS], Y[PAIRS];
    float mind[2 * PAIRS];

#pragma unroll
    for (int i = 0; i < PAIRS; i++) {
        int q = i * FPS_T + t;
        int p0 = 2 * q, p1 = 2 * q + 1;
        float4 v0 = P[p0], v1 = P[p1];
        bool va = (p0 < len), vb = (p1 < len);
        float x0 = va ? v0.x : 1e18f, y0 = va ? v0.y : 1e18f, z0 = va ? v0.z : 1e18f;
        float x1 = vb ? v1.x : 1e18f, y1 = vb ? v1.y : 1e18f, z1 = vb ? v1.z : 1e18f;
        PACK2(X[i], x0, x1);
        PACK2(Y[i], y0, y1);
        sxy[p0] = make_float2(x0, y0);
        sxy[p1] = make_float2(x1, y1);
        szp[q]  = make_float2(z0, z1);
        mind[2 * i]     = va ? 1e10f : -1e30f;
        mind[2 * i + 1] = vb ? 1e10f : -1e30f;
    }
    float4 v0 = __ldg(&P[0]);
    float wx = v0.x, wy = v0.y, wz = v0.z;
    int wpt = 0;
    if (t == 0) { s_cidx[0] = 0; g_group_len[b] = 0; }
    __syncthreads();

    for (int k = 1; k < NG; k++) {
        unsigned long long nCx, nCy, nCz;
        PACK2(nCx, -wx, -wx);
        PACK2(nCy, -wy, -wy);
        PACK2(nCz, -wz, -wz);

        float fm = -1e30f;
#pragma unroll
        for (int i = 0; i < PAIRS; i++) {
            int q = i * FPS_T + t;
            float2 zz = szp[q];
            unsigned long long Zp, dx, dy, dz, sx, sy, sz, s1, d2p;
            PACK2(Zp, zz.x, zz.y);
            ADDX2(dx, X[i], nCx);           // x - cx  (add of negated, IEEE exact)
            ADDX2(dy, Y[i], nCy);
            ADDX2(dz, Zp,  nCz);
            MULX2(sx, dx, dx);
            MULX2(sy, dy, dy);
            MULX2(sz, dz, dz);
            ADDX2(s1, sx, sy);              // (dx^2 + dy^2)
            ADDX2(d2p, s1, sz);             // ... + dz^2   (same order as scalar)
            float lo, hi;
            UNPACK2(lo, hi, d2p);
            float m0 = fminf(mind[2 * i],     lo);
            float m1 = fminf(mind[2 * i + 1], hi);
            mind[2 * i] = m0; mind[2 * i + 1] = m1;
            fm = fmaxf(fm, fmaxf(m0, m1));
        }

        // warp argmax: max value (redux), min point index among matches
        unsigned ek = encf(fm);
        unsigned wm = redux_max_u32(ek);
        unsigned mybp = 0xFFFFFFFFu;
        if (ek == wm) {                      // predicated rescan (winning lanes only)
#pragma unroll
            for (int i = PAIRS - 1; i >= 0; i--) {
                int q = i * FPS_T + t;
                if (mind[2 * i + 1] == fm) mybp = (unsigned)(2 * q + 1);
                if (mind[2 * i]     == fm) mybp = (unsigned)(2 * q);
            }
        }
        unsigned wi = redux_min_u32(mybp);
        const int par = k & 1;
        if (lane == 0)
            s_wk[par][wid] = ((unsigned long long)wm << 32) | (0xFFFFFFFFu - wi);
        __syncthreads();                     // ONE barrier per iteration

        // every warp redundantly reduces the 32 keys -> identical winner
        unsigned long long kk = s_wk[par][lane];
        unsigned khi = (unsigned)(kk >> 32), klo = (unsigned)kk;
        unsigned mh = redux_max_u32(khi);
        unsigned ml = redux_max_u32((khi == mh) ? klo : 0u);
        wpt = (int)(0xFFFFFFFFu - ml);
        float2 xy = sxy[wpt];
        float2 z2 = szp[wpt >> 1];
        wx = xy.x; wy = xy.y; wz = (wpt & 1) ? z2.y : z2.x;
        if (t == 0) s_cidx[k] = wpt;
    }
    __syncthreads();

    // tail: gather centers (all 4 channels incl. energy)
    if (t < NG) {
        int p = s_cidx[t];
        float4 v = __ldg(&P[p]);
        g_centers[b * NG + t] = v;
        if (t < CTX) ((float4*)out_centers)[b * CTX + t] = v;
    }
}

// =====================================================================
// K2: ball query, warp-per-center, MLP=8. grid (64, 8), 256 threads.
// Also accumulates g_group_len (count of groups with cnt >= GS) so the
// embedding mask can be emitted by sort_emit without a 4th kernel.
// =====================================================================
__global__ __launch_bounds__(256, 4)
void ballquery_kernel(const float4* __restrict__ pts, const int* __restrict__ lengths) {
    const int b = blockIdx.y;
    const int wid = threadIdx.x >> 5, lane = threadIdx.x & 31;
    const int gi = blockIdx.x * 8 + wid;          // center index 0..511
    const int len = lengths[b];
    const float4* __restrict__ P = pts + (size_t)b * NPTS;
    const unsigned lt = (1u << lane) - 1u;

    float4 cc = g_centers[b * NG + gi];
    const float cx = cc.x, cy = cc.y, cz = cc.z;
    unsigned long long* __restrict__ buf = g_cand + (size_t)(b * NG + gi) * UK;

    int cnt = 0;
    for (int p0 = 0; p0 < NPTS && cnt < UK; p0 += 256) {
        float4 v[8];
#pragma unroll
        for (int j = 0; j < 8; j++)                // 8 independent loads: MLP=8
            v[j] = __ldg(&P[p0 + j * 32 + lane]);
#pragma unroll
        for (int j = 0; j < 8; j++) {              // ordered ballot rounds
            int p = p0 + j * 32 + lane;
            bool pred = (p < len) && (d2_exact(v[j].x - cx, v[j].y - cy, v[j].z - cz) < R2);
            unsigned m = __ballot_sync(0xffffffffu, pred);
            if (m) {
                int rnk = cnt + __popc(m & lt);
                if (pred && rnk < UK) {
                    unsigned eb = __float_as_uint(v[j].w);
                    unsigned ekey = (eb & 0x80000000u) ? ~eb : (eb | 0x80000000u);
                    buf[rnk] = ((unsigned long long)ekey << 32)
                             | (unsigned)(0xFFFFFFFFu - (unsigned)p);
                }
                cnt += __popc(m);
                if (cnt >= UK) { cnt = UK; break; }
            }
        }
    }
    if (lane == 0) {
        g_cand_cnt[b * NG + gi] = cnt;
        if (cnt >= GS) atomicAdd(&g_group_len[b], 1);   // group fully populated
    }
}

// =====================================================================
// K3: per-group adaptive bitonic sort + emit groups/point_mask/emask.
// g_group_len is final (ballquery kernel boundary precedes this launch).
// =====================================================================
__global__ __launch_bounds__(256, 8)
void sort_emit_kernel(const float4* __restrict__ pts,
                      float* __restrict__ out_groups /* d_out */,
                      float* __restrict__ out_pmask  /* d_out + OFF_PMASK */,
                      float* __restrict__ out_emask  /* d_out + OFF_EMASK */) {
    const int gi = blockIdx.x;
    const int b  = blockIdx.y;
    const int g  = b * NG + gi;
    const int t  = threadIdx.x;

    __shared__ unsigned long long s[UK];
    const int cnt = g_cand_cnt[g];
    const unsigned long long* __restrict__ src = g_cand + (size_t)g * UK;

    int M = GS;
    while (M < cnt) M <<= 1;                       // 32..512, CTA-uniform

    for (int i = t; i < M; i += 256)
        s[i] = (i < cnt) ? src[i] : 0ull;

    for (int kk = 2; kk <= M; kk <<= 1) {
        for (int j = kk >> 1; j > 0; j >>= 1) {
            __syncthreads();
            for (int e = t; e < M; e += 256) {
                int l = e ^ j;
                if (l > e) {
                    unsigned long long a = s[e], c = s[l];
                    bool dsc = ((e & kk) == 0);
                    bool sw = dsc ? (a < c) : (a > c);
                    if (sw) { s[e] = c; s[l] = a; }
                }
            }
        }
    }
    __syncthreads();

    const int pl = min(cnt, GS);

    if (gi < CTX) {
        if (t < GS * 4) {
            int slot = t >> 2, ch = t & 3;
            int ss = (slot < pl) ? slot : 0;
            unsigned p = 0xFFFFFFFFu - (unsigned)(s[ss] & 0xFFFFFFFFull);
            const float* pp = (const float*)(pts + ((size_t)b * NPTS + p));
            out_groups[(((size_t)(b * CTX + gi)) * GS + slot) * 4 + ch] = pp[ch];
        } else if (t < GS * 4 + GS) {
            int slot = t - GS * 4;
            out_pmask[(size_t)(b * CTX + gi) * GS + slot] = (slot < pl) ? 1.0f : 0.0f;
        } else if (t == GS * 4 + GS) {
            out_emask[b * CTX + gi] = (gi < g_group_len[b]) ? 1.0f : 0.0f;
        }
    }
}

// =====================================================================
extern "C" void kernel_launch(void* const* d_in, const int* in_sizes, int n_in,
                              void* d_out, int out_size) {
    const float4* pts = (const float4*)d_in[0];   // (8,16384,4) f32
    const int*   lens = (const int*)d_in[1];      // (8,)
    float* out = (float*)d_out;

    cudaFuncSetAttribute(fps_kernel,
                         cudaFuncAttributeMaxDynamicSharedMemorySize, FPS_SMEM);

    fps_kernel<<<BB, FPS_T, FPS_SMEM>>>(pts, lens, out + OFF_CENTERS);
    ballquery_kernel<<<dim3(64, BB), 256>>>(pts, lens);
    sort_emit_kernel<<<dim3(NG, BB), 256>>>(pts, out + OFF_GROUPS,
                                            out + OFF_PMASK, out + OFF_EMASK);
}